// round 17
// baseline (speedup 1.0000x reference)
#include <cuda_runtime.h>
#include <cstdint>

#define BB   32
#define SS   1024
#define HH   256
#define G4   1024   // 4*H
#define H2   512    // 2*H

typedef unsigned long long ull;

// ---------------- f32x2 helpers (Blackwell packed fp32, 2 MAC/inst) -------
__device__ __forceinline__ ull ffma2(ull a, ull b, ull c)
{
    ull d;
    asm("fma.rn.f32x2 %0, %1, %2, %3;" : "=l"(d) : "l"(a), "l"(b), "l"(c));
    return d;
}
__device__ __forceinline__ ull pack_dup(float a)
{
    ull d;
    unsigned u = __float_as_uint(a);
    asm("mov.b64 %0, {%1, %1};" : "=l"(d) : "r"(u));
    return d;
}
__device__ __forceinline__ float2 unpack2(ull v)
{
    unsigned lo, hi;
    asm("mov.b64 {%0, %1}, %2;" : "=r"(lo), "=r"(hi) : "l"(v));
    return make_float2(__uint_as_float(lo), __uint_as_float(hi));
}

// ---------------- scoped release/acquire flag ops -------------------------
__device__ __forceinline__ void st_release_gpu(int* p, int v)
{
    asm volatile("st.release.gpu.global.u32 [%0], %1;" :: "l"(p), "r"(v) : "memory");
}
__device__ __forceinline__ int ld_acquire_gpu(const int* p)
{
    int v;
    asm volatile("ld.acquire.gpu.global.u32 %0, [%1];" : "=r"(v) : "l"(p) : "memory");
    return v;
}
__device__ __forceinline__ void red_release_add(int* p, int v)
{
    asm volatile("red.release.gpu.global.add.s32 [%0], %1;" :: "l"(p), "r"(v) : "memory");
}

// ------------------------- scratch (device globals; no allocs) -------------
__device__ float g_gates_f[(size_t)SS * BB * G4];   // layer-0 fwd gates
__device__ float g_gates_b[(size_t)SS * BB * G4];   // layer-0 bwd gates
__device__ float g_c_fa[(size_t)SS * BB * G4];      // l1f contrib from x_fwd (+bias)
__device__ float g_c_fb[(size_t)SS * BB * G4];      // l1f contrib from x_bwd
__device__ float g_c_ba[(size_t)SS * BB * G4];      // l1b contrib from x_fwd (+bias)
__device__ float g_c_bb[(size_t)SS * BB * G4];      // l1b contrib from x_bwd
__device__ float g_xout [(size_t)SS * BB * H2];     // layer-0 output [s][b][512]
// replicated h flags: [layer][dir][consumer(64)][producer(64)]
__device__ int   g_flags [2 * 2 * 64 * 64];
// gates0 tile counters: [z(2)][sblock(256)] (8 tiles per entry when complete)
__device__ int   g_gcnt  [2 * 256];
// h exchange: [dir][parity][b(32)][64] float4
__device__ float g_hx    [2 * 2 * 32 * 256];

#define SMRAW_BYTES 36352

// --------------------------------------------------------------------------
__global__ void zero_flags_k()
{
    int i = blockIdx.x * blockDim.x + threadIdx.x;
    if (i < 2 * 2 * 64 * 64) g_flags[i] = 0;
    else if (i < 2 * 2 * 64 * 64 + 2 * 256) g_gcnt[i - 2 * 2 * 64 * 64] = 0;
}

// --------------------------------------------------------------------------
__device__ __forceinline__ float sigm_f(float x)
{
    float e = __expf(-x);
    return __fdividef(1.f, 1.f + e);
}
__device__ __forceinline__ float tanh_f(float x)
{
    float xc = fminf(fmaxf(x, -30.f), 30.f);
    float e = __expf(-2.f * xc);
    return __fdividef(1.f - e, 1.f + e);
}

// --------------------------------------------------------------------------
// Shared GEMM tile core: 128x128 tile, f32x2, double-buffered smem.
// A rows come from arow0/arow1 (+64); W rows from wrow0/wrow1. KT k-tiles.
// Epilogue: bias (optional) + store to recurrence-layout buffer C2.
__device__ __forceinline__ void gemm_tile_core(
    float* As, float* Bs, int tid,
    const float* arow0, const float* arow1,
    const float* wrow0, const float* wrow1, int KT,
    const float* bih, const float* bhh, int add_bias,
    float* C2, int m0, int n0)
{
    const int tx = tid & 15;
    const int ty = tid >> 4;
    const int lr = tid >> 2;
    const int lc = (tid & 3) << 2;

    ull accp[8][4];
#pragma unroll
    for (int i = 0; i < 8; ++i)
#pragma unroll
        for (int j = 0; j < 4; ++j) accp[i][j] = 0ull;

    float4 a0 = __ldcg((const float4*)(arow0 + lc));
    float4 a1 = __ldcg((const float4*)(arow1 + lc));
    float4 b0 = *(const float4*)(wrow0 + lc);
    float4 b1 = *(const float4*)(wrow1 + lc);

    for (int kt = 0; kt < KT; ++kt) {
        float* Ab = As + (kt & 1) * 16 * 132;
        float* Bb = Bs + (kt & 1) * 16 * 132;
        Ab[(lc + 0) * 132 + lr] = a0.x; Ab[(lc + 1) * 132 + lr] = a0.y;
        Ab[(lc + 2) * 132 + lr] = a0.z; Ab[(lc + 3) * 132 + lr] = a0.w;
        Ab[(lc + 0) * 132 + lr + 64] = a1.x; Ab[(lc + 1) * 132 + lr + 64] = a1.y;
        Ab[(lc + 2) * 132 + lr + 64] = a1.z; Ab[(lc + 3) * 132 + lr + 64] = a1.w;
        Bb[(lc + 0) * 132 + lr] = b0.x; Bb[(lc + 1) * 132 + lr] = b0.y;
        Bb[(lc + 2) * 132 + lr] = b0.z; Bb[(lc + 3) * 132 + lr] = b0.w;
        Bb[(lc + 0) * 132 + lr + 64] = b1.x; Bb[(lc + 1) * 132 + lr + 64] = b1.y;
        Bb[(lc + 2) * 132 + lr + 64] = b1.z; Bb[(lc + 3) * 132 + lr + 64] = b1.w;
        __syncthreads();
        if (kt + 1 < KT) {
            int k0 = (kt + 1) << 4;
            a0 = __ldcg((const float4*)(arow0 + k0 + lc));
            a1 = __ldcg((const float4*)(arow1 + k0 + lc));
            b0 = *(const float4*)(wrow0 + k0 + lc);
            b1 = *(const float4*)(wrow1 + k0 + lc);
        }
#pragma unroll
        for (int k = 0; k < 16; ++k) {
            float4 af0 = *(const float4*)&Ab[k * 132 + ty * 4];
            float4 af1 = *(const float4*)&Ab[k * 132 + 64 + ty * 4];
            ulonglong2 bv0 = *(const ulonglong2*)&Bb[k * 132 + tx * 4];
            ulonglong2 bv1 = *(const ulonglong2*)&Bb[k * 132 + 64 + tx * 4];
            ull bp[4] = {bv0.x, bv0.y, bv1.x, bv1.y};
            float a_[8] = {af0.x, af0.y, af0.z, af0.w, af1.x, af1.y, af1.z, af1.w};
#pragma unroll
            for (int i = 0; i < 8; ++i) {
                ull ad = pack_dup(a_[i]);
#pragma unroll
                for (int j = 0; j < 4; ++j)
                    accp[i][j] = ffma2(ad, bp[j], accp[i][j]);
            }
        }
    }

#pragma unroll
    for (int qi = 0; qi < 2; ++qi) {
#pragma unroll
        for (int i = 0; i < 4; ++i) {
            int m = m0 + qi * 64 + ty * 4 + i;
            int s = m >> 5, b = m & 31;
#pragma unroll
            for (int qj = 0; qj < 2; ++qj) {
                int n = n0 + qj * 64 + tx * 4;
                float2 p0 = unpack2(accp[qi * 4 + i][qj * 2 + 0]);
                float2 p1 = unpack2(accp[qi * 4 + i][qj * 2 + 1]);
                float4 v;
                if (add_bias) {
                    v.x = p0.x + bih[n + 0] + bhh[n + 0];
                    v.y = p0.y + bih[n + 1] + bhh[n + 1];
                    v.z = p1.x + bih[n + 2] + bhh[n + 2];
                    v.w = p1.y + bih[n + 3] + bhh[n + 3];
                } else {
                    v.x = p0.x; v.y = p0.y; v.z = p1.x; v.w = p1.y;
                }
                int g  = n >> 8;
                int ub = (n & 255) >> 2;
                *(float4*)&C2[(((size_t)s * 64 + ub) * 32 + b) * 16 + g * 4] = v;
            }
        }
    }
}

// --------------------------------------------------------------------------
// Recurrence body. DUAL: sum two gate-contribution buffers.
// GATED: warp-0-local acquire-poll on gates0 tile counter before gx loads.
template <int DUAL, int GATED>
__device__ __forceinline__ void rec_body(
    char* smraw, int bid,
    const float* gA, const float* gB,
    const float* gA2, const float* gB2,
    const float* WhhF, const float* WhhB,
    const float* mask, float* xout,
    float* hn_out, float* cn_out,
    int* flags, float* hx, const int* gcnt, int out_bs)
{
    float4* sh_h4 = (float4*)smraw;                 // 32*66
    float*  sh_g  = (float*)(smraw + 32 * 66 * 16); // 32*20

    const int tid  = threadIdx.x;
    const int dir  = bid >> 6;
    const int cb   = bid & 63;
    const int u0   = cb * 4;
    const int bg   = tid >> 5;
    const int lane = tid & 31;
    const int rg   = lane >> 3;
    const int ks   = lane & 7;

    const float* g1 = dir ? gB  : gA;
    const float* g2 = dir ? gB2 : gA2;
    const float* Whh = dir ? WhhB : WhhF;
    int* fl_my   = flags + (dir * 64 + cb) * 64;
    int* fl_base = flags + dir * 64 * 64;

    ull w[4][16];
#pragma unroll
    for (int r = 0; r < 4; ++r) {
        const float* wr = Whh + (size_t)(rg * HH + u0 + r) * HH + ks * 32;
#pragma unroll
        for (int f = 0; f < 8; ++f) {
            ulonglong2 v = *(const ulonglong2*)(wr + f * 4);
            w[r][f * 2 + 0] = v.x;
            w[r][f * 2 + 1] = v.y;
        }
    }

    float4 c4 = make_float4(0.f, 0.f, 0.f, 0.f);

    for (int t = 0; t < SS; ++t) {
        const int s = dir ? (SS - 1 - t) : t;

        float4 gxa, gxb, gxc, gxd;
        float mt = 0.f;
        if (tid < 32) {
            if (GATED) {                 // warp-local gates-ready gate
                if (tid == 0) {
                    const int* gc = gcnt + dir * 256 + (s >> 2);
                    while (ld_acquire_gpu(gc) < 8) { __nanosleep(128); }
                }
                __syncwarp();
            }
            const size_t go = (((size_t)s * 64 + cb) * 32 + tid) * 16;
            const float* gp = g1 + go;
            gxa = *(const float4*)(gp + 0);
            gxb = *(const float4*)(gp + 4);
            gxc = *(const float4*)(gp + 8);
            gxd = *(const float4*)(gp + 12);
            if (DUAL) {
                const float* gq = g2 + go;
                float4 qa = *(const float4*)(gq + 0);
                float4 qb = *(const float4*)(gq + 4);
                float4 qc = *(const float4*)(gq + 8);
                float4 qd = *(const float4*)(gq + 12);
                gxa.x += qa.x; gxa.y += qa.y; gxa.z += qa.z; gxa.w += qa.w;
                gxb.x += qb.x; gxb.y += qb.y; gxb.z += qb.z; gxb.w += qb.w;
                gxc.x += qc.x; gxc.y += qc.y; gxc.z += qc.z; gxc.w += qc.w;
                gxd.x += qd.x; gxd.y += qd.y; gxd.z += qd.z; gxd.w += qd.w;
            }
            mt = __ldg(mask + tid * SS + s);
        }

        if (t > 0) {
            if (tid < 64) {
                const int* p = fl_my + tid;
                while (ld_acquire_gpu(p) < t) { }
            }
            __syncthreads();

            const float4* src = (const float4*)hx + ((size_t)dir * 2 + ((t - 1) & 1)) * 2048;
            for (int q = tid; q < 2048; q += 256) {
                int b  = q >> 6;
                int k4 = q & 63;
                int kss = k4 >> 3, j = k4 & 7;
                float4 v = __ldcg(src + q);
                sh_h4[b * 66 + kss * 8 + ((j + kss) & 7)] = v;
            }
            __syncthreads();

            ull acc[4][4];
#pragma unroll
            for (int i = 0; i < 4; ++i)
#pragma unroll
                for (int r = 0; r < 4; ++r) acc[i][r] = 0ull;

#pragma unroll
            for (int k2 = 0; k2 < 16; ++k2) {
                const int co = (((k2 >> 1) + ks) & 7) * 2 + (k2 & 1);
#pragma unroll
                for (int i = 0; i < 4; ++i) {
                    const ull* hp = (const ull*)&sh_h4[(bg * 4 + i) * 66 + ks * 8];
                    ull h = hp[co];
#pragma unroll
                    for (int r = 0; r < 4; ++r)
                        acc[i][r] = ffma2(h, w[r][k2], acc[i][r]);
                }
            }

            float g[4][4];
#pragma unroll
            for (int i = 0; i < 4; ++i)
#pragma unroll
                for (int r = 0; r < 4; ++r) {
                    float2 u = unpack2(acc[i][r]);
                    g[i][r] = u.x + u.y;
                }
#pragma unroll
            for (int d = 1; d < 8; d <<= 1) {
#pragma unroll
                for (int i = 0; i < 4; ++i)
#pragma unroll
                    for (int r = 0; r < 4; ++r)
                        g[i][r] += __shfl_xor_sync(0xffffffffu, g[i][r], d);
            }
            if (ks == 0) {
#pragma unroll
                for (int i = 0; i < 4; ++i)
#pragma unroll
                    for (int r = 0; r < 4; ++r)
                        sh_g[(bg * 4 + i) * 20 + rg * 4 + r] = g[i][r];
            }
        } else {
            if (tid < 32) {
#pragma unroll
                for (int r = 0; r < 16; ++r) sh_g[tid * 20 + r] = 0.f;
            }
        }
        __syncthreads();

        if (tid < 32) {
            const float* gh = &sh_g[tid * 20];
            float4 hn4, cn4;
            float* hnp = &hn4.x;
            float* cnp = &cn4.x;
            float* csp = &c4.x;
            const float* gxi = &gxa.x;
            const float* gxf = &gxb.x;
            const float* gxg = &gxc.x;
            const float* gxo = &gxd.x;
#pragma unroll
            for (int u = 0; u < 4; ++u) {
                float ig = sigm_f(gxi[u] + gh[0  + u]);
                float fg = sigm_f(gxf[u] + gh[4  + u]);
                float gv = tanh_f(gxg[u] + gh[8  + u]);
                float og = sigm_f(gxo[u] + gh[12 + u]);
                float cn = fg * csp[u] + ig * gv;
                float hn = og * tanh_f(cn);
                hn *= mt;
                cn *= mt;
                csp[u] = cn;
                hnp[u] = hn;
                cnp[u] = cn;
            }
            ((float4*)hx)[((size_t)dir * 2 + (t & 1)) * 2048 + tid * 64 + cb] = hn4;
            size_t orow = out_bs ? ((size_t)tid * SS + s)
                                 : ((size_t)s * BB + tid);
            *(float4*)&xout[orow * H2 + dir * HH + u0] = hn4;
            if (t == SS - 1) {
                *(float4*)&hn_out[tid * H2 + dir * HH + u0] = hn4;
                *(float4*)&cn_out[tid * H2 + dir * HH + u0] = cn4;
            }
        }
        __syncthreads();
        if (tid < 64) {
            st_release_gpu(fl_base + tid * 64 + cb, t + 1);
        }
    }
}

// --------------------------------------------------------------------------
// gemm0 CTA: layer-0 input GEMM tile (K=256, inputs [b][s][k]), ordered by
// consumption: z=0 (fwd) s ascending, z=1 (bwd) s descending. Releases a
// per-(z, sblock) tile counter when done.
__device__ void gemm0_body(
    char* smraw, int gid,
    const float* inputs,
    const float* Wf, const float* bihf, const float* bhhf,
    const float* Wb, const float* bihb, const float* bhhb,
    float* Cf, float* Cb, int* gcnt)
{
    float* As = (float*)smraw;
    float* Bs = As + 2 * 16 * 132;

    // gid layout: [nyr(256)][z(2)][nx(8)]
    const int nyr = gid >> 4;
    const int z   = (gid >> 3) & 1;
    const int nx  = gid & 7;
    const int ny  = z ? (255 - nyr) : nyr;

    const int tid = threadIdx.x;
    const float* W   = z ? Wb   : Wf;
    const float* bih = z ? bihb : bihf;
    const float* bhh = z ? bhhb : bhhf;
    float* C2        = z ? Cb   : Cf;

    const int m0 = ny * 128;
    const int n0 = nx * 128;
    const int lr = tid >> 2;

    // a_mode 0: row m -> inputs[b][s][:]
    int m  = m0 + lr;
    int s0 = m >> 5,  b0i = m & 31;
    int m2 = m + 64;
    int s1 = m2 >> 5, b1i = m2 & 31;
    const float* arow0 = inputs + ((size_t)b0i * SS + s0) * 256;
    const float* arow1 = inputs + ((size_t)b1i * SS + s1) * 256;
    const float* wrow0 = W + (size_t)(n0 + lr)      * 256;
    const float* wrow1 = W + (size_t)(n0 + lr + 64) * 256;

    gemm_tile_core(As, Bs, tid, arow0, arow1, wrow0, wrow1, 16,
                   bih, bhh, 1, C2, m0, n0);

    __syncthreads();   // all stores done before the release
    if (tid == 0) red_release_add(gcnt + z * 256 + ny, 1);
}

// --------------------------------------------------------------------------
// gemm1 CTA: layer-1 contribution GEMM tile (split-K by direction), gated
// on layer-0 recurrence flags.
__device__ void gemm1_body(
    char* smraw, int gid,
    const float* xout, const int* flags0,
    const float* Wf, const float* bihf, const float* bhhf,
    const float* Wb, const float* bihb, const float* bhhb,
    float* c_fa, float* c_fb, float* c_ba, float* c_bb)
{
    float* As = (float*)smraw;
    float* Bs = As + 2 * 16 * 132;

    // id order == readiness order: [ny_rank(256)][z(2)][half(2)][nx(8)]
    const int nyr  = gid >> 5;
    const int z    = (gid >> 4) & 1;
    const int half = (gid >> 3) & 1;
    const int nx   = gid & 7;
    const int ny   = half ? (255 - nyr) : nyr;

    const int tid = threadIdx.x;
    const int thr = half ? (1024 - 4 * ny) : (4 * ny + 4);
    const int* prow = flags0 + half * 64 * 64 + (gid & 63) * 64;
    if (tid < 64) {
        const int* p = prow + tid;
        if (ld_acquire_gpu(p) < thr) {
            while (ld_acquire_gpu(p) < thr) { __nanosleep(1024); }
        }
    }
    __syncthreads();

    const float* W   = z ? Wb   : Wf;
    const float* bih = z ? bihb : bihf;
    const float* bhh = z ? bhhb : bhhf;
    float* C2 = z ? (half ? c_bb : c_ba) : (half ? c_fb : c_fa);

    const int m0 = ny * 128;
    const int n0 = nx * 128;
    const int koff = half * 256;
    const int lr = tid >> 2;

    const float* arow0 = xout + (size_t)(m0 + lr)      * H2 + koff;
    const float* arow1 = xout + (size_t)(m0 + lr + 64) * H2 + koff;
    const float* wrow0 = W + (size_t)(n0 + lr)      * H2 + koff;
    const float* wrow1 = W + (size_t)(n0 + lr + 64) * H2 + koff;

    gemm_tile_core(As, Bs, tid, arow0, arow1, wrow0, wrow1, 16,
                   bih, bhh, half == 0 ? 1 : 0, C2, m0, n0);
}

// --------------------------------------------------------------------------
// Mega kernel: [0,128) rec0 (gated on gemm0 counters);
// [128, 128+4096) gemm0; [128+4096, 128+4096+8192) gemm1.
__global__ void __launch_bounds__(256) mega_all(
    const float* __restrict__ inputs,
    const float* __restrict__ l0f_Wih, const float* __restrict__ l0f_bih, const float* __restrict__ l0f_bhh,
    const float* __restrict__ l0b_Wih, const float* __restrict__ l0b_bih, const float* __restrict__ l0b_bhh,
    float* __restrict__ g0f, float* __restrict__ g0b,
    const float* __restrict__ l0f_Whh, const float* __restrict__ l0b_Whh,
    const float* __restrict__ mask,
    float* __restrict__ xout, float* __restrict__ hn0, float* __restrict__ cn0,
    int* __restrict__ flags0, int* __restrict__ gcnt, float* __restrict__ hx,
    const float* __restrict__ l1f_Wih, const float* __restrict__ l1f_bih, const float* __restrict__ l1f_bhh,
    const float* __restrict__ l1b_Wih, const float* __restrict__ l1b_bih, const float* __restrict__ l1b_bhh,
    float* __restrict__ c_fa, float* __restrict__ c_fb,
    float* __restrict__ c_ba, float* __restrict__ c_bb)
{
    __shared__ __align__(16) char smraw[SMRAW_BYTES];
    const int bid = blockIdx.x;
    if (bid < 128) {
        rec_body<0, 1>(smraw, bid, g0f, g0b, nullptr, nullptr,
                       l0f_Whh, l0b_Whh, mask, xout, hn0, cn0,
                       flags0, hx, gcnt, 0);
    } else if (bid < 128 + 4096) {
        gemm0_body(smraw, bid - 128, inputs,
                   l0f_Wih, l0f_bih, l0f_bhh,
                   l0b_Wih, l0b_bih, l0b_bhh,
                   g0f, g0b, gcnt);
    } else {
        gemm1_body(smraw, bid - (128 + 4096), xout, flags0,
                   l1f_Wih, l1f_bih, l1f_bhh,
                   l1b_Wih, l1b_bih, l1b_bhh,
                   c_fa, c_fb, c_ba, c_bb);
    }
}

// --------------------------------------------------------------------------
// Layer-1 recurrence: reads summed contributions (two buffers per dir).
__global__ void __launch_bounds__(256) lstm_recur1(
    const float* __restrict__ c_fa, const float* __restrict__ c_ba,
    const float* __restrict__ c_fb, const float* __restrict__ c_bb,
    const float* __restrict__ l1f_Whh, const float* __restrict__ l1b_Whh,
    const float* __restrict__ mask,
    float* __restrict__ out, float* __restrict__ hn1, float* __restrict__ cn1,
    int* __restrict__ flags1, float* __restrict__ hx)
{
    __shared__ __align__(16) char smraw[SMRAW_BYTES];
    rec_body<1, 0>(smraw, blockIdx.x, c_fa, c_ba, c_fb, c_bb,
                   l1f_Whh, l1b_Whh, mask, out, hn1, cn1,
                   flags1, hx, nullptr, 1);
}

// --------------------------------------------------------------------------
extern "C" void kernel_launch(void* const* d_in, const int* in_sizes, int n_in,
                              void* d_out, int out_size)
{
    const float* inputs  = (const float*)d_in[0];
    const float* mask    = (const float*)d_in[1];
    const float* l0f_Wih = (const float*)d_in[2];
    const float* l0f_Whh = (const float*)d_in[3];
    const float* l0f_bih = (const float*)d_in[4];
    const float* l0f_bhh = (const float*)d_in[5];
    const float* l0b_Wih = (const float*)d_in[6];
    const float* l0b_Whh = (const float*)d_in[7];
    const float* l0b_bih = (const float*)d_in[8];
    const float* l0b_bhh = (const float*)d_in[9];
    const float* l1f_Wih = (const float*)d_in[10];
    const float* l1f_Whh = (const float*)d_in[11];
    const float* l1f_bih = (const float*)d_in[12];
    const float* l1f_bhh = (const float*)d_in[13];
    const float* l1b_Wih = (const float*)d_in[14];
    const float* l1b_Whh = (const float*)d_in[15];
    const float* l1b_bih = (const float*)d_in[16];
    const float* l1b_bhh = (const float*)d_in[17];
    float* out = (float*)d_out;

    float *p_gf, *p_gb, *p_x, *p_hx, *p_cfa, *p_cfb, *p_cba, *p_cbb;
    int *p_fl, *p_gc;
    cudaGetSymbolAddress((void**)&p_gf,  g_gates_f);
    cudaGetSymbolAddress((void**)&p_gb,  g_gates_b);
    cudaGetSymbolAddress((void**)&p_x,   g_xout);
    cudaGetSymbolAddress((void**)&p_fl,  g_flags);
    cudaGetSymbolAddress((void**)&p_gc,  g_gcnt);
    cudaGetSymbolAddress((void**)&p_hx,  g_hx);
    cudaGetSymbolAddress((void**)&p_cfa, g_c_fa);
    cudaGetSymbolAddress((void**)&p_cfb, g_c_fb);
    cudaGetSymbolAddress((void**)&p_cba, g_c_ba);
    cudaGetSymbolAddress((void**)&p_cbb, g_c_bb);

    const size_t HN_OFF = (size_t)BB * SS * H2;       // 16777216
    const size_t CN_OFF = HN_OFF + 2 * (size_t)BB * H2;
    float* hn0 = out + HN_OFF;
    float* hn1 = out + HN_OFF + (size_t)BB * H2;
    float* cn0 = out + CN_OFF;
    float* cn1 = out + CN_OFF + (size_t)BB * H2;

    zero_flags_k<<<68, 256>>>();

    // mega: gemm0 + rec0 + gemm1, all overlapped via flag gating
    mega_all<<<128 + 4096 + 8192, 256>>>(
        inputs,
        l0f_Wih, l0f_bih, l0f_bhh,
        l0b_Wih, l0b_bih, l0b_bhh,
        p_gf, p_gb,
        l0f_Whh, l0b_Whh, mask,
        p_x, hn0, cn0, p_fl, p_gc, p_hx,
        l1f_Wih, l1f_bih, l1f_bhh,
        l1b_Wih, l1b_bih, l1b_bhh,
        p_cfa, p_cfb, p_cba, p_cbb);

    // layer-1 recurrence: writes final [B,S,2H] output directly
    lstm_recur1<<<128, 256>>>(p_cfa, p_cba, p_cfb, p_cbb,
                              l1f_Whh, l1b_Whh, mask,
                              out, hn1, cn1, p_fl + 2 * 64 * 64, p_hx);
}